// round 15
// baseline (speedup 1.0000x reference)
#include <cuda_runtime.h>
#include <cstdint>

// Problem constants: B=64, MEL_MAX=2000, TEXT_MAX=256, g=0.2
#define BATCH   64
#define MEL_MAX 2000
#define TXT_MAX 256
#define A_COEF  12.5f            // 1/(2 g^2)

#define GBLK    592              // 148 SMs x 4 blocks: one exact wave
#define NTHR    256              // 8 warps; warp strides t by 8 in a segment

typedef unsigned long long u64;
typedef unsigned int u32;

// Scratch (__device__ globals — no allocation allowed)
__device__ double       g_block[GBLK];
__device__ unsigned int g_count = 0;

// ---- packed f32x2 helpers (Blackwell) ----
__device__ __forceinline__ u64 pk2(float lo, float hi) {
    u64 r; asm("mov.b64 %0,{%1,%2};" : "=l"(r) : "f"(lo), "f"(hi)); return r;
}
__device__ __forceinline__ void unpk2(u64 a, float& lo, float& hi) {
    asm("mov.b64 {%0,%1},%2;" : "=f"(lo), "=f"(hi) : "l"(a));
}
__device__ __forceinline__ u64 mul2(u64 a, u64 b) {
    u64 r; asm("mul.rn.f32x2 %0,%1,%2;" : "=l"(r) : "l"(a), "l"(b)); return r;
}
__device__ __forceinline__ u64 add2(u64 a, u64 b) {
    u64 r; asm("add.rn.f32x2 %0,%1,%2;" : "=l"(r) : "l"(a), "l"(b)); return r;
}
__device__ __forceinline__ u64 fma2(u64 a, u64 b, u64 c) {
    u64 r; asm("fma.rn.f32x2 %0,%1,%2,%3;" : "=l"(r) : "l"(a), "l"(b), "l"(c)); return r;
}

// ---------------------------------------------------------------------------
// Fused kernel, BYTE-BALANCED flat partition:
//   cost of batch b = ml_b * ceil(tl_b/8)  (32-byte chunks actually loaded)
//   block i owns cost window [i*T/G, (i+1)*T/G) -> contiguous row segments.
//   Within a segment [t_lo,t_hi): warp w handles t = t_lo + w + 8k; lane owns
//   8 contiguous text cols. Gaussian recurrent in both axes (no loop MUFU).
//   Last block (atomic ticket) reduces partials + normalizer.
// ---------------------------------------------------------------------------
__global__ __launch_bounds__(NTHR, 5) void fused_kernel(
    const float* __restrict__ pred,
    const int*   __restrict__ tlen,
    const int*   __restrict__ mlen,
    float*       __restrict__ out)
{
    __shared__ int stl[BATCH], sml[BATCH];
    __shared__ u32 sW[BATCH];

    const int lane = threadIdx.x & 31;
    const int wid  = threadIdx.x >> 5;

    if (threadIdx.x < BATCH) {
        const int tl = __ldg(&tlen[threadIdx.x]);
        const int ml = __ldg(&mlen[threadIdx.x]);
        stl[threadIdx.x] = tl;
        sml[threadIdx.x] = ml;
        sW[threadIdx.x]  = (u32)ml * (u32)((tl + 7) >> 3);
    }
    __syncthreads();

    // total cost (block-uniform walk over 64 entries)
    u32 T = 0;
    #pragma unroll 8
    for (int k = 0; k < BATCH; k++) T += sW[k];

    const u32 lo = (u32)(((u64)blockIdx.x       * T) / GBLK);
    const u32 hi = (u32)(((u64)(blockIdx.x + 1) * T) / GBLK);

    u64 sP = 0, sE = 0;   // packed accumulators: sum p, sum E*p

    // ---- walk batches; process row segments inside [lo,hi) ----
    u32 P = 0;
    for (int b = 0; b < BATCH; b++) {
        const u32 W  = sW[b];
        const u32 Pn = P + W;
        if (P < hi && Pn > lo && W > 0) {
            const int tl  = stl[b];
            const int ml  = sml[b];
            const u32 cpr = (u32)((tl + 7) >> 3);
            const int t_lo = (lo > P) ? (int)((lo - P + cpr - 1) / cpr) : 0;
            int t_hi = (hi < Pn) ? (int)((hi - P + cpr - 1) / cpr) : ml;
            if (t_hi > ml) t_hi = ml;

            if (t_lo < t_hi) {
                // ---- segment-invariant constants ----
                const float inv_tl = 1.0f / (float)tl;
                const float inv_ml = 1.0f / (float)ml;
                const int   n0     = lane * 8;
                const float alpha0 = (float)n0 * inv_tl;
                const float ca     = 2.0f * A_COEF * inv_tl * inv_ml;
                const float cb     = -A_COEF * inv_tl * inv_tl * (float)(2 * n0 + 1);
                const float q2     = __expf(-2.0f * A_COEF * inv_tl * inv_tl);
                const float q2sq   = q2 * q2;
                const float q8     = q2sq * q2sq;
                const u64   Q4     = pk2(q8, q8);

                int count = tl - n0;
                if (count < 0) count = 0; if (count > 8) count = 8;
                const bool pred_lo = (count > 0);
                const bool pred_hi = (count > 4);
                const u64 mk0 = pk2(count > 0 ? 1.0f : 0.0f, count > 1 ? 1.0f : 0.0f);
                const u64 mk1 = pk2(count > 2 ? 1.0f : 0.0f, count > 3 ? 1.0f : 0.0f);
                const u64 mk2 = pk2(count > 4 ? 1.0f : 0.0f, count > 5 ? 1.0f : 0.0f);
                const u64 mk3 = pk2(count > 6 ? 1.0f : 0.0f, count > 7 ? 1.0f : 0.0f);

                // ---- t-direction seed recurrence (stride 8) ----
                const int   t0  = t_lo + wid;
                const float di  = 8.0f * inv_ml;
                const float u0v = alpha0 - (float)t0 * inv_ml;
                float S  = __expf(-2.0f * A_COEF * di * di);
                float E0 = __expf(-A_COEF * u0v * u0v);
                float rr = __expf(2.0f * A_COEF * di * u0v - A_COEF * di * di);
                float m0 = __expf(fmaf(ca, (float)t0, cb));
                float RM = __expf(8.0f * ca);
                if (!pred_lo) { E0 = 0.0f; rr = 0.0f; m0 = 0.0f; RM = 0.0f; }

                auto chain = [&](float E0v, float m0v, ulonglong2 vlo, ulonglong2 vhi) {
                    const float ms = m0v * m0v;
                    const float m2 = ms * q2;
                    u64 E2 = pk2(E0v, E0v * m0v);
                    u64 M2 = pk2(m2, m2 * q2sq);
                    u64 mp;
                    mp = mul2(vlo.x, mk0); sP = add2(sP, mp); sE = fma2(E2, mp, sE);
                    E2 = mul2(E2, M2); M2 = mul2(M2, Q4);
                    mp = mul2(vlo.y, mk1); sP = add2(sP, mp); sE = fma2(E2, mp, sE);
                    E2 = mul2(E2, M2); M2 = mul2(M2, Q4);
                    mp = mul2(vhi.x, mk2); sP = add2(sP, mp); sE = fma2(E2, mp, sE);
                    E2 = mul2(E2, M2);
                    mp = mul2(vhi.y, mk3); sP = add2(sP, mp); sE = fma2(E2, mp, sE);
                };

                const float* rowp = pred + (size_t)b * (MEL_MAX * TXT_MAX)
                                         + (size_t)t0 * TXT_MAX + n0;
                int t = t0;

                // ---- main loop: rows t and t+8 per iteration ----
                for (; t + 8 < t_hi; t += 16, rowp += (size_t)16 * TXT_MAX) {
                    ulonglong2 a0; a0.x = 0; a0.y = 0;
                    ulonglong2 b0; b0.x = 0; b0.y = 0;
                    ulonglong2 a1; a1.x = 0; a1.y = 0;
                    ulonglong2 b1; b1.x = 0; b1.y = 0;
                    const float* r1 = rowp + (size_t)8 * TXT_MAX;
                    if (pred_lo) { a0 = *(const ulonglong2*)rowp;       a1 = *(const ulonglong2*)r1; }
                    if (pred_hi) { b0 = *(const ulonglong2*)(rowp + 4); b1 = *(const ulonglong2*)(r1 + 4); }

                    const float E0a = E0, m0a = m0;
                    E0 *= rr; rr *= S; m0 *= RM;
                    const float E0b = E0, m0b = m0;
                    E0 *= rr; rr *= S; m0 *= RM;

                    chain(E0a, m0a, a0, b0);
                    chain(E0b, m0b, a1, b1);
                }

                // ---- tail: at most one row for this warp ----
                if (t < t_hi) {
                    ulonglong2 a0; a0.x = 0; a0.y = 0;
                    ulonglong2 b0; b0.x = 0; b0.y = 0;
                    if (pred_lo) a0 = *(const ulonglong2*)rowp;
                    if (pred_hi) b0 = *(const ulonglong2*)(rowp + 4);
                    chain(E0, m0, a0, b0);
                }
            }
        }
        P = Pn;
    }

    // ---- combine: loss = sum p - sum E p ----
    float x0, x1, y0, y1;
    unpk2(sP, x0, x1);
    unpk2(sE, y0, y1);
    float tot = (x0 + x1) - (y0 + y1);

    #pragma unroll
    for (int o = 16; o > 0; o >>= 1)
        tot += __shfl_xor_sync(0xFFFFFFFFu, tot, o);

    __shared__ double wsum[8];
    if (lane == 0) wsum[wid] = (double)tot;
    __syncthreads();

    __shared__ bool amLast;
    if (threadIdx.x == 0) {
        double sacc = 0.0;
        #pragma unroll
        for (int k = 0; k < 8; k++) sacc += wsum[k];
        g_block[blockIdx.x] = sacc;
        __threadfence();
        amLast = (atomicAdd(&g_count, 1u) == GBLK - 1);
    }
    __syncthreads();

    // ---- last block: final reduction + normalizer ----
    if (amLast) {
        __threadfence();
        double sv = 0.0;
        for (int k = threadIdx.x; k < GBLK; k += NTHR)
            sv += __ldcg(&g_block[k]);
        double sa = 0.0;
        if (threadIdx.x < BATCH)
            sa = (double)stl[threadIdx.x] * (double)sml[threadIdx.x];

        #pragma unroll
        for (int o = 16; o > 0; o >>= 1) {
            sv += __shfl_xor_sync(0xFFFFFFFFu, sv, o);
            sa += __shfl_xor_sync(0xFFFFFFFFu, sa, o);
        }

        __shared__ double fv[8], fa[8];
        if (lane == 0) { fv[wid] = sv; fa[wid] = sa; }
        __syncthreads();

        if (threadIdx.x == 0) {
            double tv = 0.0, ta = 0.0;
            #pragma unroll
            for (int k = 0; k < 8; k++) { tv += fv[k]; ta += fa[k]; }
            out[0] = (float)(tv / ta);   // attention_weight = 1.0
            g_count = 0;                 // reset for next graph replay
        }
    }
}

// ---------------------------------------------------------------------------
// Inputs (metadata order): targets (unused), predictions, text_lengths,
// mel_lengths. Output: single float.
// ---------------------------------------------------------------------------
extern "C" void kernel_launch(void* const* d_in, const int* in_sizes, int n_in,
                              void* d_out, int out_size)
{
    (void)in_sizes; (void)n_in; (void)out_size;
    const float* pred = (const float*)d_in[1];
    const int*   tlen = (const int*)d_in[2];
    const int*   mlen = (const int*)d_in[3];
    float*       out  = (float*)d_out;

    fused_kernel<<<GBLK, NTHR>>>(pred, tlen, mlen, out);
}

// round 16
// speedup vs baseline: 1.7431x; 1.7431x over previous
#include <cuda_runtime.h>
#include <cstdint>

// Problem constants: B=64, MEL_MAX=2000, TEXT_MAX=256, g=0.2
#define BATCH   64
#define MEL_MAX 2000
#define TXT_MAX 256
#define A_COEF  12.5f            // 1/(2 g^2)

#define SLABS   16               // t-slabs per batch
#define SLAB    125              // rows per slab (16*125 = 2000)
#define NBLK    (SLABS * BATCH)  // 1024 blocks
#define NTHR    256              // 8 warps; warp strides t by 8 within slab

typedef unsigned long long u64;

// Scratch (__device__ globals — no allocation allowed)
__device__ double       g_block[NBLK];
__device__ unsigned int g_count = 0;

// ---- packed f32x2 helpers (Blackwell) ----
__device__ __forceinline__ u64 pk2(float lo, float hi) {
    u64 r; asm("mov.b64 %0,{%1,%2};" : "=l"(r) : "f"(lo), "f"(hi)); return r;
}
__device__ __forceinline__ void unpk2(u64 a, float& lo, float& hi) {
    asm("mov.b64 {%0,%1},%2;" : "=f"(lo), "=f"(hi) : "l"(a));
}
__device__ __forceinline__ u64 mul2(u64 a, u64 b) {
    u64 r; asm("mul.rn.f32x2 %0,%1,%2;" : "=l"(r) : "l"(a), "l"(b)); return r;
}
__device__ __forceinline__ u64 add2(u64 a, u64 b) {
    u64 r; asm("add.rn.f32x2 %0,%1,%2;" : "=l"(r) : "l"(a), "l"(b)); return r;
}
__device__ __forceinline__ u64 fma2(u64 a, u64 b, u64 c) {
    u64 r; asm("fma.rn.f32x2 %0,%1,%2,%3;" : "=l"(r) : "l"(a), "l"(b), "l"(c)); return r;
}
// fire-and-forget L2 prefetch (no register, no scoreboard)
__device__ __forceinline__ void pfL2(const float* p) {
    asm volatile("prefetch.global.L2 [%0];" :: "l"(p));
}

// ---------------------------------------------------------------------------
// Fused kernel, slab-balanced (structure of the 16.9us best kernel) plus
// per-lane predicated prefetch.global.L2 at distance 32 rows: in-flight
// bytes are added via the L2 prefetch queue (zero register cost), so the
// demand LDGs hit L2 (~250cyc) instead of DRAM (~380+cyc).
// Block (x, b) owns t in [125x, min(125(x+1),ml)); warp w: t = 125x + w + 8k.
// Lane owns 8 contiguous text positions. Gaussian recurrent in both axes
// (no MUFU in the loop). Last block (atomic ticket) finalizes.
// ---------------------------------------------------------------------------
__global__ __launch_bounds__(NTHR, 5) void fused_kernel(
    const float* __restrict__ pred,
    const int*   __restrict__ tlen,
    const int*   __restrict__ mlen,
    float*       __restrict__ out)
{
    const int lane = threadIdx.x & 31;
    const int wid  = threadIdx.x >> 5;
    const int b    = blockIdx.y;
    const int x    = blockIdx.x;

    const int ml    = __ldg(&mlen[b]);
    const int tbase = x * SLAB;

    u64 sP = 0, sE = 0;   // packed accumulators: sum p, sum E*p

    if (tbase < ml) {
        const int tl   = __ldg(&tlen[b]);
        const int tend = (tbase + SLAB < ml) ? tbase + SLAB : ml;

        // ---- loop-invariant constants ----
        const float inv_tl = 1.0f / (float)tl;
        const float inv_ml = 1.0f / (float)ml;
        const int   n0     = lane * 8;
        const float alpha0 = (float)n0 * inv_tl;
        const float ca     = 2.0f * A_COEF * inv_tl * inv_ml;
        const float cb     = -A_COEF * inv_tl * inv_tl * (float)(2 * n0 + 1);
        const float q2     = __expf(-2.0f * A_COEF * inv_tl * inv_tl);
        const float q2sq   = q2 * q2;
        const float q8     = q2sq * q2sq;
        const u64   Q4     = pk2(q8, q8);

        int count = tl - n0; if (count < 0) count = 0; if (count > 8) count = 8;
        const bool pred_lo = (count > 0);
        const bool pred_hi = (count > 4);
        const u64 mk0 = pk2(count > 0 ? 1.0f : 0.0f, count > 1 ? 1.0f : 0.0f);
        const u64 mk1 = pk2(count > 2 ? 1.0f : 0.0f, count > 3 ? 1.0f : 0.0f);
        const u64 mk2 = pk2(count > 4 ? 1.0f : 0.0f, count > 5 ? 1.0f : 0.0f);
        const u64 mk3 = pk2(count > 6 ? 1.0f : 0.0f, count > 7 ? 1.0f : 0.0f);

        // ---- t-direction seed recurrence (stride 8) ----
        const int   t0  = tbase + wid;
        const float di  = 8.0f * inv_ml;
        const float u0v = alpha0 - (float)t0 * inv_ml;
        float S  = __expf(-2.0f * A_COEF * di * di);
        float E0 = __expf(-A_COEF * u0v * u0v);
        float rr = __expf(2.0f * A_COEF * di * u0v - A_COEF * di * di);
        float m0 = __expf(fmaf(ca, (float)t0, cb));
        float RM = __expf(8.0f * ca);
        if (!pred_lo) { E0 = 0.0f; rr = 0.0f; m0 = 0.0f; RM = 0.0f; }

        // column chain for one row (packed even/odd recurrence)
        auto chain = [&](float E0v, float m0v, ulonglong2 lo, ulonglong2 hi) {
            const float ms = m0v * m0v;
            const float m2 = ms * q2;
            u64 E2 = pk2(E0v, E0v * m0v);
            u64 M2 = pk2(m2, m2 * q2sq);
            u64 mp;
            mp = mul2(lo.x, mk0); sP = add2(sP, mp); sE = fma2(E2, mp, sE);
            E2 = mul2(E2, M2); M2 = mul2(M2, Q4);
            mp = mul2(lo.y, mk1); sP = add2(sP, mp); sE = fma2(E2, mp, sE);
            E2 = mul2(E2, M2); M2 = mul2(M2, Q4);
            mp = mul2(hi.x, mk2); sP = add2(sP, mp); sE = fma2(E2, mp, sE);
            E2 = mul2(E2, M2);
            mp = mul2(hi.y, mk3); sP = add2(sP, mp); sE = fma2(E2, mp, sE);
        };

        const float* rowp = pred + (size_t)b * (MEL_MAX * TXT_MAX)
                                 + (size_t)t0 * TXT_MAX + n0;
        int t = t0;

        // ---- prologue: prefetch the first 2 iterations' rows (t0..t0+24) ----
        if (pred_lo) {
            if (t0      < tend) pfL2(rowp);
            if (t0 +  8 < tend) pfL2(rowp + (size_t)8  * TXT_MAX);
            if (t0 + 16 < tend) pfL2(rowp + (size_t)16 * TXT_MAX);
            if (t0 + 24 < tend) pfL2(rowp + (size_t)24 * TXT_MAX);
        }

        // ---- main loop: rows t and t+8; prefetch rows t+32, t+40 ----
        for (; t + 8 < tend; t += 16, rowp += (size_t)16 * TXT_MAX) {
            if (t + 40 < tend && pred_lo) {
                pfL2(rowp + (size_t)32 * TXT_MAX);
                pfL2(rowp + (size_t)40 * TXT_MAX);
            }

            ulonglong2 a0; a0.x = 0; a0.y = 0;
            ulonglong2 b0; b0.x = 0; b0.y = 0;
            ulonglong2 a1; a1.x = 0; a1.y = 0;
            ulonglong2 b1; b1.x = 0; b1.y = 0;
            const float* r1 = rowp + (size_t)8 * TXT_MAX;
            if (pred_lo) { a0 = *(const ulonglong2*)rowp;       a1 = *(const ulonglong2*)r1; }
            if (pred_hi) { b0 = *(const ulonglong2*)(rowp + 4); b1 = *(const ulonglong2*)(r1 + 4); }

            const float E0a = E0, m0a = m0;
            E0 *= rr; rr *= S; m0 *= RM;
            const float E0b = E0, m0b = m0;
            E0 *= rr; rr *= S; m0 *= RM;

            chain(E0a, m0a, a0, b0);
            chain(E0b, m0b, a1, b1);
        }

        // ---- tail: at most one row ----
        if (t < tend) {
            ulonglong2 a0; a0.x = 0; a0.y = 0;
            ulonglong2 b0; b0.x = 0; b0.y = 0;
            if (pred_lo) a0 = *(const ulonglong2*)rowp;
            if (pred_hi) b0 = *(const ulonglong2*)(rowp + 4);
            chain(E0, m0, a0, b0);
        }
    }

    // ---- combine: loss = sum p - sum E p ----
    float x0, x1, y0, y1;
    unpk2(sP, x0, x1);
    unpk2(sE, y0, y1);
    float tot = (x0 + x1) - (y0 + y1);

    #pragma unroll
    for (int o = 16; o > 0; o >>= 1)
        tot += __shfl_xor_sync(0xFFFFFFFFu, tot, o);

    __shared__ double wsum[8];
    if (lane == 0) wsum[wid] = (double)tot;
    __syncthreads();

    __shared__ bool amLast;
    const int bid = blockIdx.y * SLABS + blockIdx.x;
    if (threadIdx.x == 0) {
        double sacc = 0.0;
        #pragma unroll
        for (int k = 0; k < 8; k++) sacc += wsum[k];
        g_block[bid] = sacc;
        __threadfence();
        amLast = (atomicAdd(&g_count, 1u) == NBLK - 1);
    }
    __syncthreads();

    // ---- last block: final reduction + normalizer ----
    if (amLast) {
        __threadfence();
        double sv = 0.0;
        for (int k = threadIdx.x; k < NBLK; k += NTHR)
            sv += __ldcg(&g_block[k]);
        double sa = 0.0;
        if (threadIdx.x < BATCH)
            sa = (double)__ldg(&tlen[threadIdx.x]) * (double)__ldg(&mlen[threadIdx.x]);

        #pragma unroll
        for (int o = 16; o > 0; o >>= 1) {
            sv += __shfl_xor_sync(0xFFFFFFFFu, sv, o);
            sa += __shfl_xor_sync(0xFFFFFFFFu, sa, o);
        }

        __shared__ double fv[8], fa[8];
        if (lane == 0) { fv[wid] = sv; fa[wid] = sa; }
        __syncthreads();

        if (threadIdx.x == 0) {
            double tv = 0.0, ta = 0.0;
            #pragma unroll
            for (int k = 0; k < 8; k++) { tv += fv[k]; ta += fa[k]; }
            out[0] = (float)(tv / ta);   // attention_weight = 1.0
            g_count = 0;                 // reset for next graph replay
        }
    }
}

// ---------------------------------------------------------------------------
// Inputs (metadata order): targets (unused), predictions, text_lengths,
// mel_lengths. Output: single float.
// ---------------------------------------------------------------------------
extern "C" void kernel_launch(void* const* d_in, const int* in_sizes, int n_in,
                              void* d_out, int out_size)
{
    (void)in_sizes; (void)n_in; (void)out_size;
    const float* pred = (const float*)d_in[1];
    const int*   tlen = (const int*)d_in[2];
    const int*   mlen = (const int*)d_in[3];
    float*       out  = (float*)d_out;

    dim3 grid(SLABS, BATCH);
    fused_kernel<<<grid, NTHR>>>(pred, tlen, mlen, out);
}